// round 15
// baseline (speedup 1.0000x reference)
#include <cuda_runtime.h>
#include <cuda_fp16.h>
#include <math.h>

#define NN   256
#define CIN  128
#define HH   4
#define DD   32
#define NPOS (NN*NN)
#define FULL 0xffffffffu
#define LOG2E 1.4426950408889634f

// ---------------- scratch (device globals) ----------------
__device__ __half g_Wh[CIN][512];          // [c][e] fp16: e<128 wq*scale*log2e, <256 wk, <384 wv, <512 wg
__device__ float  g_wbt[HH][CIN];          // tri-bias weights f32 (x log2e)
__device__ __half g_Woh[CIN][CIN];         // [e][c] = w_o[c][e] fp16
__device__ __half g_q[NN][HH][NN][DD];
__device__ __half g_k[NN][HH][NN][DD];
__device__ __half g_v[NN][HH][NN][DD];
__device__ __half g_gate[(size_t)NPOS*CIN];
__device__ __half g_tbh[HH][NN][NN];       // [h][query][key] fp16, pre-scaled by log2e
__device__ __half g_o[(size_t)NPOS*CIN];

// ---------------- helpers ----------------
__device__ __forceinline__ unsigned cvta_s(const void* p) {
    return (unsigned)__cvta_generic_to_shared(p);
}
__device__ __forceinline__ void cpa16(unsigned dst, const void* src) {
    asm volatile("cp.async.cg.shared.global [%0], [%1], 16;" :: "r"(dst), "l"(src) : "memory");
}
#define CPA_COMMIT() asm volatile("cp.async.commit_group;" ::: "memory")
#define CPA_WAIT0()  asm volatile("cp.async.wait_group 0;" ::: "memory")

__device__ __forceinline__ void ldsm4(uint4& d, unsigned a) {
    asm volatile("ldmatrix.sync.aligned.m8n8.x4.shared.b16 {%0,%1,%2,%3}, [%4];"
                 : "=r"(d.x), "=r"(d.y), "=r"(d.z), "=r"(d.w) : "r"(a));
}
__device__ __forceinline__ void ldsm4t(uint4& d, unsigned a) {
    asm volatile("ldmatrix.sync.aligned.m8n8.x4.trans.shared.b16 {%0,%1,%2,%3}, [%4];"
                 : "=r"(d.x), "=r"(d.y), "=r"(d.z), "=r"(d.w) : "r"(a));
}
// NON-volatile: lets ptxas schedule loads/MUFU across mmas.
__device__ __forceinline__ void mma16(float4& d, unsigned a0, unsigned a1, unsigned a2, unsigned a3,
                                      unsigned b0, unsigned b1) {
    asm("mma.sync.aligned.m16n8k16.row.col.f32.f16.f16.f32 "
        "{%0,%1,%2,%3},{%4,%5,%6,%7},{%8,%9},{%0,%1,%2,%3};"
        : "+f"(d.x), "+f"(d.y), "+f"(d.z), "+f"(d.w)
        : "r"(a0), "r"(a1), "r"(a2), "r"(a3), "r"(b0), "r"(b1));
}
__device__ __forceinline__ unsigned packh2(float lo, float hi) {
    unsigned r;
    asm("cvt.rn.f16x2.f32 %0, %1, %2;" : "=r"(r) : "f"(hi), "f"(lo));
    return r;
}
// raw 2^x (log2e pre-folded into scores)
__device__ __forceinline__ float ex2f(float x) {
    float r;
    asm("ex2.approx.f32 %0, %1;" : "=f"(r) : "f"(x));
    return r;
}

// ---------------- weight prep ----------------
__global__ void prep_kernel(const float* __restrict__ wb, const float* __restrict__ wq,
                            const float* __restrict__ wk, const float* __restrict__ wv,
                            const float* __restrict__ wg, const float* __restrict__ wo) {
    int idx = blockIdx.x * blockDim.x + threadIdx.x;
    if (idx < CIN * 512) {
        int c = idx >> 9, e = idx & 511;
        float val;
        if      (e < 128) val = wq[e * CIN + c] * (0.17677669529663687f * LOG2E);
        else if (e < 256) val = wk[(e - 128) * CIN + c];
        else if (e < 384) val = wv[(e - 256) * CIN + c];
        else              val = wg[(e - 384) * CIN + c];
        g_Wh[c][e] = __float2half(val);
    }
    if (idx < HH * CIN) {
        int h = idx >> 7, c = idx & 127;
        g_wbt[h][c] = wb[h * CIN + c] * LOG2E;
    }
    if (idx < CIN * CIN) {
        int e = idx >> 7, c = idx & 127;
        g_Woh[e][c] = __float2half(wo[c * CIN + e]);
    }
}

// ---------------- fused LN + {q,k,v,gate} fp16-mma projection + tri-bias ----------------
struct LnSmem {
    __half xs[128][136];       // 128 data cols + 8 pad (row 272B)
    __half Bs[2][128][72];     // cp.async double-buffered 64-col weight chunks (row 144B)
    float mu[128], rs[128];
};

__global__ __launch_bounds__(256) void lnproj_kernel(const float* __restrict__ x,
                                                     const float* __restrict__ lnw,
                                                     const float* __restrict__ lnb,
                                                     const float* __restrict__ bg) {
    extern __shared__ char sraw[];
    LnSmem& S = *(LnSmem*)sraw;

    int t = threadIdx.x;
    int p0 = blockIdx.x * 128;
    int w = t >> 5, lane = t & 31;
    int gid = lane >> 2, tig = lane & 3;

    // kick off async load of weight chunk 0 (independent of LN work)
    for (int f = t; f < 1024; f += 256) {
        int k = f >> 3, c8 = (f & 7) * 8;
        cpa16(cvta_s(&S.Bs[0][k][c8]), &g_Wh[k][c8]);
    }
    CPA_COMMIT();

    // LN stats
    for (int rr = 0; rr < 16; rr++) {
        int r = w * 16 + rr;
        const float* xp = x + (size_t)(p0 + r) * CIN;
        float v0 = xp[lane], v1 = xp[lane + 32], v2 = xp[lane + 64], v3 = xp[lane + 96];
        float s = v0 + v1 + v2 + v3;
        float q = v0 * v0 + v1 * v1 + v2 * v2 + v3 * v3;
        #pragma unroll
        for (int off = 16; off; off >>= 1) {
            s += __shfl_down_sync(FULL, s, off);
            q += __shfl_down_sync(FULL, q, off);
        }
        if (lane == 0) {
            float m = s * (1.f / 128.f);
            S.mu[r] = m;
            S.rs[r] = rsqrtf(q * (1.f / 128.f) - m * m + 1e-5f);
        }
    }
    __syncthreads();

    // normalize -> fp16 xs
    for (int idx = t * 4; idx < 128 * 128; idx += 1024) {
        int r = idx >> 7, c = idx & 127;
        float4 xv = *(const float4*)(x + (size_t)(p0 + r) * CIN + c);
        float4 wv = *(const float4*)(lnw + c);
        float4 bv = *(const float4*)(lnb + c);
        float m = S.mu[r], rs = S.rs[r];
        *(__half2*)&S.xs[r][c]     = __floats2half2_rn((xv.x - m) * rs * wv.x + bv.x,
                                                       (xv.y - m) * rs * wv.y + bv.y);
        *(__half2*)&S.xs[r][c + 2] = __floats2half2_rn((xv.z - m) * rs * wv.z + bv.z,
                                                       (xv.w - m) * rs * wv.w + bv.w);
    }
    CPA_WAIT0();
    __syncthreads();

    int wm = w >> 1, wn = w & 1;              // warp tile: 32 rows x 32 cols of 64-chunk
    int m8 = lane >> 3, r8 = lane & 7;

    unsigned aBase = cvta_s(&S.xs[wm * 32 + (m8 & 1) * 8 + r8][(m8 >> 1) * 8]);
    unsigned bBase[2];
    bBase[0] = cvta_s(&S.Bs[0][(m8 & 1) * 8 + r8][wn * 32 + (m8 >> 1) * 8]);
    bBase[1] = cvta_s(&S.Bs[1][(m8 & 1) * 8 + r8][wn * 32 + (m8 >> 1) * 8]);

    int p_lo0 = p0 + wm * 32 + gid;
    int ii = p_lo0 >> 8;

    for (int nc = 0; nc < 8; nc++) {
        int cur = nc & 1;
        // async prefetch of next chunk overlaps with this chunk's mmas
        if (nc < 7) {
            for (int f = t; f < 1024; f += 256) {
                int k = f >> 3, c8 = (f & 7) * 8;
                cpa16(cvta_s(&S.Bs[cur ^ 1][k][c8]), &g_Wh[k][(nc + 1) * 64 + c8]);
            }
            CPA_COMMIT();
        }

        float4 acc[2][4];
        #pragma unroll
        for (int mt = 0; mt < 2; mt++)
            #pragma unroll
            for (int nt = 0; nt < 4; nt++) acc[mt][nt] = make_float4(0.f, 0.f, 0.f, 0.f);

        unsigned bb = bBase[cur];
        #pragma unroll
        for (int ks = 0; ks < 8; ks++) {
            uint4 A0, A1, B0, B1;
            ldsm4(A0, aBase + ks * 32);
            ldsm4(A1, aBase + ks * 32 + 4352);     // +16 rows (16*272B)
            ldsm4t(B0, bb + ks * 2304);            // +16 k-rows (16*144B)
            ldsm4t(B1, bb + ks * 2304 + 32);       // +16 n-cols
            mma16(acc[0][0], A0.x, A0.y, A0.z, A0.w, B0.x, B0.y);
            mma16(acc[0][1], A0.x, A0.y, A0.z, A0.w, B0.z, B0.w);
            mma16(acc[0][2], A0.x, A0.y, A0.z, A0.w, B1.x, B1.y);
            mma16(acc[0][3], A0.x, A0.y, A0.z, A0.w, B1.z, B1.w);
            mma16(acc[1][0], A1.x, A1.y, A1.z, A1.w, B0.x, B0.y);
            mma16(acc[1][1], A1.x, A1.y, A1.z, A1.w, B0.z, B0.w);
            mma16(acc[1][2], A1.x, A1.y, A1.z, A1.w, B1.x, B1.y);
            mma16(acc[1][3], A1.x, A1.y, A1.z, A1.w, B1.z, B1.w);
        }

        // epilogue to gmem
        int sel = nc >> 1;   // 0=q 1=k 2=v 3=gate
        #pragma unroll
        for (int mt = 0; mt < 2; mt++) {
            int p_lo = p_lo0 + mt * 16;
            int jj_lo = p_lo & 255, jj_hi = jj_lo + 8;
            #pragma unroll
            for (int nt = 0; nt < 4; nt++) {
                int e0 = nc * 64 + wn * 32 + nt * 8 + 2 * tig;
                int loc = e0 & 127;
                int hh = loc >> 5, d0 = loc & 31;
                float4 a = acc[mt][nt];
                if (sel == 0) {
                    *(__half2*)&g_q[ii][hh][jj_lo][d0] = __floats2half2_rn(a.x, a.y);
                    *(__half2*)&g_q[ii][hh][jj_hi][d0] = __floats2half2_rn(a.z, a.w);
                } else if (sel == 1) {
                    *(__half2*)&g_k[ii][hh][jj_lo][d0] = __floats2half2_rn(a.x, a.y);
                    *(__half2*)&g_k[ii][hh][jj_hi][d0] = __floats2half2_rn(a.z, a.w);
                } else if (sel == 2) {
                    *(__half2*)&g_v[ii][hh][jj_lo][d0] = __floats2half2_rn(a.x, a.y);
                    *(__half2*)&g_v[ii][hh][jj_hi][d0] = __floats2half2_rn(a.z, a.w);
                } else {
                    float2 bg2 = *(const float2*)(bg + loc);
                    float glx = 1.f / (1.f + __expf(-(a.x + bg2.x)));
                    float gly = 1.f / (1.f + __expf(-(a.y + bg2.y)));
                    float ghx = 1.f / (1.f + __expf(-(a.z + bg2.x)));
                    float ghy = 1.f / (1.f + __expf(-(a.w + bg2.y)));
                    *(__half2*)(g_gate + (size_t)p_lo * CIN + loc) = __floats2half2_rn(glx, gly);
                    *(__half2*)(g_gate + ((size_t)p_lo + 8) * CIN + loc) = __floats2half2_rn(ghx, ghy);
                }
            }
        }

        if (nc < 7) CPA_WAIT0();
        __syncthreads();
    }

    // triangle bias (fp16 out, pre-scaled by log2e via g_wbt)
    for (int pp = t; pp < 512; pp += 256) {
        int rr = pp >> 2, hh = pp & 3;
        const float* wv = g_wbt[hh];
        float a = 0.f;
        #pragma unroll 16
        for (int c = 0; c < 128; c += 2) {
            float2 fx = __half22float2(*(__half2*)&S.xs[rr][c]);
            a += fx.x * wv[c] + fx.y * wv[c + 1];
        }
        int p = p0 + rr;
        g_tbh[hh][p >> 8][p & 255] = __float2half(a);
    }
}

// ---------------- fp16-mma flash attention + gating ----------------
// CTA = (i, h): 256 threads, 8 warps, warp owns 32 queries. K/V staged once.
// Tri-bias: PER-WARP double-buffered cp.async staging (warp w owns Tb rows
// w*32..w*32+31) -> no CTA-wide barrier in the mainloop, only __syncwarp.
// Softmax denominator via ones-column mma.
struct AttnSmem {
    __half Qs[256][40];       // 20 KB
    __half Ks[256][40];       // 20 KB
    __half Vs[256][40];       // 20 KB
    __half Tb[2][256][40];    // 40 KB: tb tile [q][32k] + 8 pad (row 80B, cp.async-aligned)
    float mbs[256];           // 1 KB
};

__global__ __launch_bounds__(256, 2) void attn_kernel(const float* __restrict__ mask) {
    extern __shared__ char sraw[];
    AttnSmem& S = *(AttnSmem*)sraw;

    int bid = blockIdx.x;
    int i = bid >> 2;
    int h = bid & 3;
    int t = threadIdx.x;
    int w = t >> 5, lane = t & 31;
    int gid = lane >> 2, tig = lane & 3;

    const __half* qg = &g_q[i][h][0][0];
    const __half* kg = &g_k[i][h][0][0];
    const __half* vg = &g_v[i][h][0][0];
    const __half* tb_g = &g_tbh[h][0][0];

    for (int f = t; f < 1024; f += 256) {
        int r = f >> 2, c8 = (f & 3) * 8;
        cpa16(cvta_s(&S.Qs[r][c8]), qg + r * 32 + c8);
        cpa16(cvta_s(&S.Ks[r][c8]), kg + r * 32 + c8);
        cpa16(cvta_s(&S.Vs[r][c8]), vg + r * 32 + c8);
    }
    // tb tile for kb=0: warp-private rows (warp w stages rows w*32..w*32+31)
    {
        int qr = w * 32 + lane;
        const __half* src = tb_g + qr * NN;
        unsigned dst = cvta_s(&S.Tb[0][qr][0]);
        cpa16(dst,      src);
        cpa16(dst + 16, src + 8);
        cpa16(dst + 32, src + 16);
        cpa16(dst + 48, src + 24);
    }
    CPA_COMMIT();
    S.mbs[t] = (1e9f * LOG2E) * (mask[i * NN + t] - 1.0f);
    CPA_WAIT0();
    __syncthreads();   // K/V/Q staged by all threads -> one CTA barrier before mainloop

    int m8 = lane >> 3, r8 = lane & 7;

    // Q fragments: warp rows w*32..w*32+31, 2 m-tiles x 2 ksteps
    unsigned qA = cvta_s(&S.Qs[w * 32 + (m8 & 1) * 8 + r8][(m8 >> 1) * 8]);
    uint4 aq[2][2];
    #pragma unroll
    for (int mt = 0; mt < 2; mt++) {
        ldsm4(aq[mt][0], qA + mt * 1280);        // +16 rows (16*80B)
        ldsm4(aq[mt][1], qA + mt * 1280 + 32);   // +16 cols (d16-31)
    }

    unsigned kA = cvta_s(&S.Ks[(m8 & 1) * 8 + r8][(m8 >> 1) * 8]);
    unsigned vA = cvta_s(&S.Vs[(m8 & 1) * 8 + r8][(m8 >> 1) * 8]);

    float4 oacc[2][4];
    float4 lacc[2];
    #pragma unroll
    for (int mt = 0; mt < 2; mt++) {
        #pragma unroll
        for (int n = 0; n < 4; n++) oacc[mt][n] = make_float4(0.f, 0.f, 0.f, 0.f);
        lacc[mt] = make_float4(0.f, 0.f, 0.f, 0.f);
    }
    // ones-column B fragment: B[k][0]=1 else 0 -> lanes with gid==0 hold {1,1}
    unsigned bone = (gid == 0) ? 0x3C003C00u : 0u;

    int q_row0 = w * 32 + gid;     // mt adds +16, hi adds +8
    int cur = 0;

    for (int kb = 0; kb < 8; kb++) {
        int kbase = kb * 32;

        // prefetch next tb tile: warp-private rows, own cp.async group
        if (kb < 7) {
            int qr = w * 32 + lane;
            const __half* src = tb_g + qr * NN + kbase + 32;
            unsigned dst = cvta_s(&S.Tb[cur ^ 1][qr][0]);
            cpa16(dst,      src);
            cpa16(dst + 16, src + 8);
            cpa16(dst + 32, src + 16);
            cpa16(dst + 48, src + 24);
            CPA_COMMIT();
        }

        // S = Q @ K^T for 32 keys (K [key][d] col-major kxn -> NON-trans ldsm)
        float4 s[2][4];
        #pragma unroll
        for (int mt = 0; mt < 2; mt++)
            #pragma unroll
            for (int nt = 0; nt < 4; nt++) s[mt][nt] = make_float4(0.f, 0.f, 0.f, 0.f);

        #pragma unroll
        for (int ntp = 0; ntp < 2; ntp++) {
            unsigned ka = kA + (kbase + ntp * 16) * 80;
            uint4 B0, B1;
            ldsm4(B0, ka);
            ldsm4(B1, ka + 32);
            #pragma unroll
            for (int mt = 0; mt < 2; mt++) {
                mma16(s[mt][2 * ntp],     aq[mt][0].x, aq[mt][0].y, aq[mt][0].z, aq[mt][0].w, B0.x, B0.z);
                mma16(s[mt][2 * ntp],     aq[mt][1].x, aq[mt][1].y, aq[mt][1].z, aq[mt][1].w, B1.x, B1.z);
                mma16(s[mt][2 * ntp + 1], aq[mt][0].x, aq[mt][0].y, aq[mt][0].z, aq[mt][0].w, B0.y, B0.w);
                mma16(s[mt][2 * ntp + 1], aq[mt][1].x, aq[mt][1].y, aq[mt][1].z, aq[mt][1].w, B1.y, B1.w);
            }
        }

        // V fragments hoisted: independent of S, LDSM latency hides under exp below
        uint4 Vf[2][2];
        #pragma unroll
        for (int ktp = 0; ktp < 2; ktp++) {
            unsigned va = vA + (kbase + ktp * 16) * 80;
            ldsm4t(Vf[ktp][0], va);
            ldsm4t(Vf[ktp][1], va + 32);
        }

        // bias (tb from smem) + 2^x + pack to fp16 A-fragments
        unsigned pa[2][2][4];
        #pragma unroll
        for (int mt = 0; mt < 2; mt++) {
            int qlo = q_row0 + mt * 16;
            #pragma unroll
            for (int nt = 0; nt < 4; nt++) {
                int lk = nt * 8 + 2 * tig;
                float2 tl = __half22float2(*(__half2*)&S.Tb[cur][qlo][lk]);
                float2 th = __half22float2(*(__half2*)&S.Tb[cur][qlo + 8][lk]);
                int c0 = kbase + lk;
                float mb0 = S.mbs[c0], mb1 = S.mbs[c0 + 1];
                float px = ex2f(s[mt][nt].x + tl.x + mb0);
                float py = ex2f(s[mt][nt].y + tl.y + mb1);
                float pz = ex2f(s[mt][nt].z + th.x + mb0);
                float pw = ex2f(s[mt][nt].w + th.y + mb1);
                int ktp = nt >> 1;
                if (!(nt & 1)) {
                    pa[mt][ktp][0] = packh2(px, py);
                    pa[mt][ktp][1] = packh2(pz, pw);
                } else {
                    pa[mt][ktp][2] = packh2(px, py);
                    pa[mt][ktp][3] = packh2(pz, pw);
                }
            }
        }

        // O += P @ V, and l += P @ ones (extra column)
        #pragma unroll
        for (int ktp = 0; ktp < 2; ktp++) {
            #pragma unroll
            for (int mt = 0; mt < 2; mt++) {
                mma16(oacc[mt][0], pa[mt][ktp][0], pa[mt][ktp][1], pa[mt][ktp][2], pa[mt][ktp][3], Vf[ktp][0].x, Vf[ktp][0].y);
                mma16(oacc[mt][1], pa[mt][ktp][0], pa[mt][ktp][1], pa[mt][ktp][2], pa[mt][ktp][3], Vf[ktp][0].z, Vf[ktp][0].w);
                mma16(oacc[mt][2], pa[mt][ktp][0], pa[mt][ktp][1], pa[mt][ktp][2], pa[mt][ktp][3], Vf[ktp][1].x, Vf[ktp][1].y);
                mma16(oacc[mt][3], pa[mt][ktp][0], pa[mt][ktp][1], pa[mt][ktp][2], pa[mt][ktp][3], Vf[ktp][1].z, Vf[ktp][1].w);
                mma16(lacc[mt],    pa[mt][ktp][0], pa[mt][ktp][1], pa[mt][ktp][2], pa[mt][ktp][3], bone, bone);
            }
        }

        // wait for this warp's own tb prefetch; no CTA barrier needed
        if (kb < 7) {
            CPA_WAIT0();
            __syncwarp();
        }
        cur ^= 1;
    }

    // finalize + gated store (l broadcast from tig==0 lanes)
    #pragma unroll
    for (int mt = 0; mt < 2; mt++) {
        float ll = __shfl_sync(FULL, lacc[mt].x, lane & ~3);
        float lh = __shfl_sync(FULL, lacc[mt].z, lane & ~3);
        float inv_lo = 1.f / ll, inv_hi = 1.f / lh;

        int q_lo = q_row0 + mt * 16, q_hi = q_lo + 8;
        size_t base_lo = ((size_t)(i * NN + q_lo)) * CIN + h * DD;
        size_t base_hi = ((size_t)(i * NN + q_hi)) * CIN + h * DD;
        #pragma unroll
        for (int ntd = 0; ntd < 4; ntd++) {
            int d0 = ntd * 8 + 2 * tig;
            float2 gl = __half22float2(*(__half2*)(g_gate + base_lo + d0));
            float2 gh = __half22float2(*(__half2*)(g_gate + base_hi + d0));
            *(__half2*)(g_o + base_lo + d0) =
                __floats2half2_rn(oacc[mt][ntd].x * inv_lo * gl.x, oacc[mt][ntd].y * inv_lo * gl.y);
            *(__half2*)(g_o + base_hi + d0) =
                __floats2half2_rn(oacc[mt][ntd].z * inv_hi * gh.x, oacc[mt][ntd].w * inv_hi * gh.y);
        }
    }
}

// ---------------- fp16-mma output projection: split-N (128 rows x 64 cols per CTA) ----------------
struct OutSmem {
    __half os[128][136];    // full 128-col activations
    __half Ws[128][72];     // this CTA's 64 weight cols
};

__global__ __launch_bounds__(256, 3) void outproj_kernel(float* __restrict__ out,
                                                         const float* __restrict__ bo) {
    extern __shared__ char sraw[];
    OutSmem& S = *(OutSmem*)sraw;

    int bid = blockIdx.x;
    int p0 = (bid >> 1) * 128;
    int n0 = (bid & 1) * 64;
    int t = threadIdx.x;
    int w = t >> 5, lane = t & 31;
    int gid = lane >> 2, tig = lane & 3;

    for (int f = t; f < 2048; f += 256) {
        int r = f >> 4, c8 = (f & 15) * 8;
        cpa16(cvta_s(&S.os[r][c8]), g_o + (size_t)(p0 + r) * CIN + c8);
    }
    for (int f = t; f < 1024; f += 256) {
        int r = f >> 3, c8 = (f & 7) * 8;
        cpa16(cvta_s(&S.Ws[r][c8]), &g_Woh[r][n0 + c8]);
    }
    CPA_COMMIT();
    CPA_WAIT0();
    __syncthreads();

    int wm = w >> 1, wn = w & 1;           // warp tile 32 rows x 32 cols
    int m8 = lane >> 3, r8 = lane & 7;

    unsigned aBase = cvta_s(&S.os[wm * 32 + (m8 & 1) * 8 + r8][(m8 >> 1) * 8]);
    unsigned bBase = cvta_s(&S.Ws[(m8 & 1) * 8 + r8][wn * 32 + (m8 >> 1) * 8]);

    float4 acc[2][4];
    #pragma unroll
    for (int mt = 0; mt < 2; mt++)
        #pragma unroll
        for (int nt = 0; nt < 4; nt++) acc[mt][nt] = make_float4(0.f, 0.f, 0.f, 0.f);

    #pragma unroll
    for (int ks = 0; ks < 8; ks++) {
        uint4 A0, A1, B0, B1;
        ldsm4(A0, aBase + ks * 32);
        ldsm4(A1, aBase + ks * 32 + 4352);   // +16 rows (16*272B)
        ldsm4t(B0, bBase + ks * 2304);       // +16 k-rows (16*144B)
        ldsm4t(B1, bBase + ks * 2304 + 32);  // +16 n-cols
        mma16(acc[0][0], A0.x, A0.y, A0.z, A0.w, B0.x, B0.y);
        mma16(acc[0][1], A0.x, A0.y, A0.z, A0.w, B0.z, B0.w);
        mma16(acc[0][2], A0.x, A0.y, A0.z, A0.w, B1.x, B1.y);
        mma16(acc[0][3], A0.x, A0.y, A0.z, A0.w, B1.z, B1.w);
        mma16(acc[1][0], A1.x, A1.y, A1.z, A1.w, B0.x, B0.y);
        mma16(acc[1][1], A1.x, A1.y, A1.z, A1.w, B0.z, B0.w);
        mma16(acc[1][2], A1.x, A1.y, A1.z, A1.w, B1.x, B1.y);
        mma16(acc[1][3], A1.x, A1.y, A1.z, A1.w, B1.z, B1.w);
    }

    #pragma unroll
    for (int mt = 0; mt < 2; mt++) {
        int p_lo = p0 + wm * 32 + mt * 16 + gid;
        int p_hi = p_lo + 8;
        #pragma unroll
        for (int nt = 0; nt < 4; nt++) {
            int c0 = n0 + wn * 32 + nt * 8 + 2 * tig;
            float2 bo2 = *(const float2*)(bo + c0);
            *(float2*)(out + (size_t)p_lo * CIN + c0) =
                make_float2(acc[mt][nt].x + bo2.x, acc[mt][nt].y + bo2.y);
            *(float2*)(out + (size_t)p_hi * CIN + c0) =
                make_float2(acc[mt][nt].z + bo2.x, acc[mt][nt].w + bo2.y);
        }
    }
}

extern "C" void kernel_launch(void* const* d_in, const int* in_sizes, int n_in,
                              void* d_out, int out_size) {
    (void)in_sizes; (void)n_in; (void)out_size;
    const float* x    = (const float*)d_in[0];
    const float* mask = (const float*)d_in[1];
    const float* lnw  = (const float*)d_in[2];
    const float* lnb  = (const float*)d_in[3];
    const float* wb   = (const float*)d_in[4];
    const float* wq   = (const float*)d_in[5];
    const float* wk   = (const float*)d_in[6];
    const float* wv   = (const float*)d_in[7];
    const float* wg   = (const float*)d_in[8];
    const float* bg   = (const float*)d_in[9];
    const float* wo   = (const float*)d_in[10];
    const float* bo   = (const float*)d_in[11];
    float* out = (float*)d_out;

    cudaFuncSetAttribute(lnproj_kernel,  cudaFuncAttributeMaxDynamicSharedMemorySize, (int)sizeof(LnSmem));
    cudaFuncSetAttribute(attn_kernel,    cudaFuncAttributeMaxDynamicSharedMemorySize, (int)sizeof(AttnSmem));
    cudaFuncSetAttribute(outproj_kernel, cudaFuncAttributeMaxDynamicSharedMemorySize, (int)sizeof(OutSmem));

    prep_kernel<<<256, 256>>>(wb, wq, wk, wv, wg, wo);
    lnproj_kernel<<<512, 256, sizeof(LnSmem)>>>(x, lnw, lnb, bg);
    attn_kernel<<<1024, 256, sizeof(AttnSmem)>>>(mask);
    outproj_kernel<<<1024, 256, sizeof(OutSmem)>>>(out, bo);
}

// round 17
// speedup vs baseline: 1.0483x; 1.0483x over previous
#include <cuda_runtime.h>
#include <cuda_fp16.h>
#include <math.h>

#define NN   256
#define CIN  128
#define HH   4
#define DD   32
#define NPOS (NN*NN)
#define FULL 0xffffffffu
#define LOG2E 1.4426950408889634f

// ---------------- scratch (device globals) ----------------
__device__ __half g_Wh[CIN][512];          // [c][e] fp16: e<128 wq*scale*log2e, <256 wk, <384 wv, <512 wg
__device__ float  g_wbt[HH][CIN];          // tri-bias weights f32 (x log2e)
__device__ __half g_Woh[CIN][CIN];         // [e][c] = w_o[c][e] fp16
__device__ __half g_q[NN][HH][NN][DD];
__device__ __half g_k[NN][HH][NN][DD];
__device__ __half g_v[NN][HH][NN][DD];
__device__ __half g_gate[(size_t)NPOS*CIN];
__device__ __half g_tbh[HH][NN][NN];       // [h][query][key] fp16, pre-scaled by log2e
__device__ __half g_o[(size_t)NPOS*CIN];

// ---------------- helpers ----------------
__device__ __forceinline__ unsigned cvta_s(const void* p) {
    return (unsigned)__cvta_generic_to_shared(p);
}
__device__ __forceinline__ void cpa16(unsigned dst, const void* src) {
    asm volatile("cp.async.cg.shared.global [%0], [%1], 16;" :: "r"(dst), "l"(src) : "memory");
}
#define CPA_COMMIT() asm volatile("cp.async.commit_group;" ::: "memory")
#define CPA_WAIT0()  asm volatile("cp.async.wait_group 0;" ::: "memory")

__device__ __forceinline__ void ldsm4(uint4& d, unsigned a) {
    asm volatile("ldmatrix.sync.aligned.m8n8.x4.shared.b16 {%0,%1,%2,%3}, [%4];"
                 : "=r"(d.x), "=r"(d.y), "=r"(d.z), "=r"(d.w) : "r"(a));
}
__device__ __forceinline__ void ldsm4t(uint4& d, unsigned a) {
    asm volatile("ldmatrix.sync.aligned.m8n8.x4.trans.shared.b16 {%0,%1,%2,%3}, [%4];"
                 : "=r"(d.x), "=r"(d.y), "=r"(d.z), "=r"(d.w) : "r"(a));
}
// NON-volatile: lets ptxas schedule loads/MUFU across mmas.
__device__ __forceinline__ void mma16(float4& d, unsigned a0, unsigned a1, unsigned a2, unsigned a3,
                                      unsigned b0, unsigned b1) {
    asm("mma.sync.aligned.m16n8k16.row.col.f32.f16.f16.f32 "
        "{%0,%1,%2,%3},{%4,%5,%6,%7},{%8,%9},{%0,%1,%2,%3};"
        : "+f"(d.x), "+f"(d.y), "+f"(d.z), "+f"(d.w)
        : "r"(a0), "r"(a1), "r"(a2), "r"(a3), "r"(b0), "r"(b1));
}
__device__ __forceinline__ unsigned packh2(float lo, float hi) {
    unsigned r;
    asm("cvt.rn.f16x2.f32 %0, %1, %2;" : "=r"(r) : "f"(hi), "f"(lo));
    return r;
}
// raw 2^x (log2e pre-folded into scores)
__device__ __forceinline__ float ex2f(float x) {
    float r;
    asm("ex2.approx.f32 %0, %1;" : "=f"(r) : "f"(x));
    return r;
}
// packed fp16 2^x on a half2 (one MUFU op for two values)
__device__ __forceinline__ unsigned h2ex2(unsigned x) {
    unsigned r;
    asm("ex2.approx.f16x2 %0, %1;" : "=r"(r) : "r"(x));
    return r;
}

// ---------------- weight prep ----------------
__global__ void prep_kernel(const float* __restrict__ wb, const float* __restrict__ wq,
                            const float* __restrict__ wk, const float* __restrict__ wv,
                            const float* __restrict__ wg, const float* __restrict__ wo) {
    int idx = blockIdx.x * blockDim.x + threadIdx.x;
    if (idx < CIN * 512) {
        int c = idx >> 9, e = idx & 511;
        float val;
        if      (e < 128) val = wq[e * CIN + c] * (0.17677669529663687f * LOG2E);
        else if (e < 256) val = wk[(e - 128) * CIN + c];
        else if (e < 384) val = wv[(e - 256) * CIN + c];
        else              val = wg[(e - 384) * CIN + c];
        g_Wh[c][e] = __float2half(val);
    }
    if (idx < HH * CIN) {
        int h = idx >> 7, c = idx & 127;
        g_wbt[h][c] = wb[h * CIN + c] * LOG2E;
    }
    if (idx < CIN * CIN) {
        int e = idx >> 7, c = idx & 127;
        g_Woh[e][c] = __float2half(wo[c * CIN + e]);
    }
}

// ---------------- fused LN + {q,k,v,gate} fp16-mma projection + tri-bias ----------------
struct LnSmem {
    __half xs[128][136];       // 128 data cols + 8 pad (row 272B)
    __half Bs[2][128][72];     // cp.async double-buffered 64-col weight chunks (row 144B)
    float mu[128], rs[128];
};

__global__ __launch_bounds__(256) void lnproj_kernel(const float* __restrict__ x,
                                                     const float* __restrict__ lnw,
                                                     const float* __restrict__ lnb,
                                                     const float* __restrict__ bg) {
    extern __shared__ char sraw[];
    LnSmem& S = *(LnSmem*)sraw;

    int t = threadIdx.x;
    int p0 = blockIdx.x * 128;
    int w = t >> 5, lane = t & 31;
    int gid = lane >> 2, tig = lane & 3;

    // kick off async load of weight chunk 0 (independent of LN work)
    for (int f = t; f < 1024; f += 256) {
        int k = f >> 3, c8 = (f & 7) * 8;
        cpa16(cvta_s(&S.Bs[0][k][c8]), &g_Wh[k][c8]);
    }
    CPA_COMMIT();

    // LN stats
    for (int rr = 0; rr < 16; rr++) {
        int r = w * 16 + rr;
        const float* xp = x + (size_t)(p0 + r) * CIN;
        float v0 = xp[lane], v1 = xp[lane + 32], v2 = xp[lane + 64], v3 = xp[lane + 96];
        float s = v0 + v1 + v2 + v3;
        float q = v0 * v0 + v1 * v1 + v2 * v2 + v3 * v3;
        #pragma unroll
        for (int off = 16; off; off >>= 1) {
            s += __shfl_down_sync(FULL, s, off);
            q += __shfl_down_sync(FULL, q, off);
        }
        if (lane == 0) {
            float m = s * (1.f / 128.f);
            S.mu[r] = m;
            S.rs[r] = rsqrtf(q * (1.f / 128.f) - m * m + 1e-5f);
        }
    }
    __syncthreads();

    // normalize -> fp16 xs
    for (int idx = t * 4; idx < 128 * 128; idx += 1024) {
        int r = idx >> 7, c = idx & 127;
        float4 xv = *(const float4*)(x + (size_t)(p0 + r) * CIN + c);
        float4 wv = *(const float4*)(lnw + c);
        float4 bv = *(const float4*)(lnb + c);
        float m = S.mu[r], rs = S.rs[r];
        *(__half2*)&S.xs[r][c]     = __floats2half2_rn((xv.x - m) * rs * wv.x + bv.x,
                                                       (xv.y - m) * rs * wv.y + bv.y);
        *(__half2*)&S.xs[r][c + 2] = __floats2half2_rn((xv.z - m) * rs * wv.z + bv.z,
                                                       (xv.w - m) * rs * wv.w + bv.w);
    }
    CPA_WAIT0();
    __syncthreads();

    int wm = w >> 1, wn = w & 1;              // warp tile: 32 rows x 32 cols of 64-chunk
    int m8 = lane >> 3, r8 = lane & 7;

    unsigned aBase = cvta_s(&S.xs[wm * 32 + (m8 & 1) * 8 + r8][(m8 >> 1) * 8]);
    unsigned bBase[2];
    bBase[0] = cvta_s(&S.Bs[0][(m8 & 1) * 8 + r8][wn * 32 + (m8 >> 1) * 8]);
    bBase[1] = cvta_s(&S.Bs[1][(m8 & 1) * 8 + r8][wn * 32 + (m8 >> 1) * 8]);

    int p_lo0 = p0 + wm * 32 + gid;
    int ii = p_lo0 >> 8;

    for (int nc = 0; nc < 8; nc++) {
        int cur = nc & 1;
        // async prefetch of next chunk overlaps with this chunk's mmas
        if (nc < 7) {
            for (int f = t; f < 1024; f += 256) {
                int k = f >> 3, c8 = (f & 7) * 8;
                cpa16(cvta_s(&S.Bs[cur ^ 1][k][c8]), &g_Wh[k][(nc + 1) * 64 + c8]);
            }
            CPA_COMMIT();
        }

        float4 acc[2][4];
        #pragma unroll
        for (int mt = 0; mt < 2; mt++)
            #pragma unroll
            for (int nt = 0; nt < 4; nt++) acc[mt][nt] = make_float4(0.f, 0.f, 0.f, 0.f);

        unsigned bb = bBase[cur];
        #pragma unroll
        for (int ks = 0; ks < 8; ks++) {
            uint4 A0, A1, B0, B1;
            ldsm4(A0, aBase + ks * 32);
            ldsm4(A1, aBase + ks * 32 + 4352);     // +16 rows (16*272B)
            ldsm4t(B0, bb + ks * 2304);            // +16 k-rows (16*144B)
            ldsm4t(B1, bb + ks * 2304 + 32);       // +16 n-cols
            mma16(acc[0][0], A0.x, A0.y, A0.z, A0.w, B0.x, B0.y);
            mma16(acc[0][1], A0.x, A0.y, A0.z, A0.w, B0.z, B0.w);
            mma16(acc[0][2], A0.x, A0.y, A0.z, A0.w, B1.x, B1.y);
            mma16(acc[0][3], A0.x, A0.y, A0.z, A0.w, B1.z, B1.w);
            mma16(acc[1][0], A1.x, A1.y, A1.z, A1.w, B0.x, B0.y);
            mma16(acc[1][1], A1.x, A1.y, A1.z, A1.w, B0.z, B0.w);
            mma16(acc[1][2], A1.x, A1.y, A1.z, A1.w, B1.x, B1.y);
            mma16(acc[1][3], A1.x, A1.y, A1.z, A1.w, B1.z, B1.w);
        }

        // epilogue to gmem
        int sel = nc >> 1;   // 0=q 1=k 2=v 3=gate
        #pragma unroll
        for (int mt = 0; mt < 2; mt++) {
            int p_lo = p_lo0 + mt * 16;
            int jj_lo = p_lo & 255, jj_hi = jj_lo + 8;
            #pragma unroll
            for (int nt = 0; nt < 4; nt++) {
                int e0 = nc * 64 + wn * 32 + nt * 8 + 2 * tig;
                int loc = e0 & 127;
                int hh = loc >> 5, d0 = loc & 31;
                float4 a = acc[mt][nt];
                if (sel == 0) {
                    *(__half2*)&g_q[ii][hh][jj_lo][d0] = __floats2half2_rn(a.x, a.y);
                    *(__half2*)&g_q[ii][hh][jj_hi][d0] = __floats2half2_rn(a.z, a.w);
                } else if (sel == 1) {
                    *(__half2*)&g_k[ii][hh][jj_lo][d0] = __floats2half2_rn(a.x, a.y);
                    *(__half2*)&g_k[ii][hh][jj_hi][d0] = __floats2half2_rn(a.z, a.w);
                } else if (sel == 2) {
                    *(__half2*)&g_v[ii][hh][jj_lo][d0] = __floats2half2_rn(a.x, a.y);
                    *(__half2*)&g_v[ii][hh][jj_hi][d0] = __floats2half2_rn(a.z, a.w);
                } else {
                    float2 bg2 = *(const float2*)(bg + loc);
                    float glx = 1.f / (1.f + __expf(-(a.x + bg2.x)));
                    float gly = 1.f / (1.f + __expf(-(a.y + bg2.y)));
                    float ghx = 1.f / (1.f + __expf(-(a.z + bg2.x)));
                    float ghy = 1.f / (1.f + __expf(-(a.w + bg2.y)));
                    *(__half2*)(g_gate + (size_t)p_lo * CIN + loc) = __floats2half2_rn(glx, gly);
                    *(__half2*)(g_gate + ((size_t)p_lo + 8) * CIN + loc) = __floats2half2_rn(ghx, ghy);
                }
            }
        }

        if (nc < 7) CPA_WAIT0();
        __syncthreads();
    }

    // triangle bias (fp16 out, pre-scaled by log2e via g_wbt)
    for (int pp = t; pp < 512; pp += 256) {
        int rr = pp >> 2, hh = pp & 3;
        const float* wv = g_wbt[hh];
        float a = 0.f;
        #pragma unroll 16
        for (int c = 0; c < 128; c += 2) {
            float2 fx = __half22float2(*(__half2*)&S.xs[rr][c]);
            a += fx.x * wv[c] + fx.y * wv[c + 1];
        }
        int p = p0 + rr;
        g_tbh[hh][p >> 8][p & 255] = __float2half(a);
    }
}

// ---------------- fp16-mma flash attention + gating ----------------
// CTA = (i, h): 256 threads, 8 warps, warp owns 32 queries. K/V staged once;
// tri-bias tile double-buffered via cp.async; softmax denominator via
// ones-column mma; exp via packed ex2.approx.f16x2 (args packed to fp16 first).
struct AttnSmem {
    __half Qs[256][40];       // 20 KB
    __half Ks[256][40];       // 20 KB
    __half Vs[256][40];       // 20 KB
    __half Tb[2][256][40];    // 40 KB: tb tile [q][32k] + 8 pad (row 80B, cp.async-aligned)
    float mbs[256];           // 1 KB
};

__global__ __launch_bounds__(256, 2) void attn_kernel(const float* __restrict__ mask) {
    extern __shared__ char sraw[];
    AttnSmem& S = *(AttnSmem*)sraw;

    int bid = blockIdx.x;
    int i = bid >> 2;
    int h = bid & 3;
    int t = threadIdx.x;
    int w = t >> 5, lane = t & 31;
    int gid = lane >> 2, tig = lane & 3;

    const __half* qg = &g_q[i][h][0][0];
    const __half* kg = &g_k[i][h][0][0];
    const __half* vg = &g_v[i][h][0][0];
    const __half* tb_g = &g_tbh[h][0][0];

    for (int f = t; f < 1024; f += 256) {
        int r = f >> 2, c8 = (f & 3) * 8;
        cpa16(cvta_s(&S.Qs[r][c8]), qg + r * 32 + c8);
        cpa16(cvta_s(&S.Ks[r][c8]), kg + r * 32 + c8);
        cpa16(cvta_s(&S.Vs[r][c8]), vg + r * 32 + c8);
    }
    // tb tile for kb=0
    for (int f = t; f < 1024; f += 256) {
        int q = f >> 2, c = (f & 3) * 8;
        cpa16(cvta_s(&S.Tb[0][q][c]), tb_g + q * NN + c);
    }
    CPA_COMMIT();
    S.mbs[t] = (1e9f * LOG2E) * (mask[i * NN + t] - 1.0f);
    CPA_WAIT0();
    __syncthreads();

    int m8 = lane >> 3, r8 = lane & 7;

    // Q fragments: warp rows w*32..w*32+31, 2 m-tiles x 2 ksteps
    unsigned qA = cvta_s(&S.Qs[w * 32 + (m8 & 1) * 8 + r8][(m8 >> 1) * 8]);
    uint4 aq[2][2];
    #pragma unroll
    for (int mt = 0; mt < 2; mt++) {
        ldsm4(aq[mt][0], qA + mt * 1280);        // +16 rows (16*80B)
        ldsm4(aq[mt][1], qA + mt * 1280 + 32);   // +16 cols (d16-31)
    }

    unsigned kA = cvta_s(&S.Ks[(m8 & 1) * 8 + r8][(m8 >> 1) * 8]);
    unsigned vA = cvta_s(&S.Vs[(m8 & 1) * 8 + r8][(m8 >> 1) * 8]);

    float4 oacc[2][4];
    float4 lacc[2];
    #pragma unroll
    for (int mt = 0; mt < 2; mt++) {
        #pragma unroll
        for (int n = 0; n < 4; n++) oacc[mt][n] = make_float4(0.f, 0.f, 0.f, 0.f);
        lacc[mt] = make_float4(0.f, 0.f, 0.f, 0.f);
    }
    // ones-column B fragment: B[k][0]=1 else 0 -> lanes with gid==0 hold {1,1}
    unsigned bone = (gid == 0) ? 0x3C003C00u : 0u;

    int q_row0 = w * 32 + gid;     // mt adds +16, hi adds +8
    int cur = 0;

    for (int kb = 0; kb < 8; kb++) {
        int kbase = kb * 32;

        // prefetch next tb tile (overlaps with this block's compute)
        if (kb < 7) {
            int nb = kbase + 32;
            for (int f = t; f < 1024; f += 256) {
                int q = f >> 2, c = (f & 3) * 8;
                cpa16(cvta_s(&S.Tb[cur ^ 1][q][c]), tb_g + q * NN + nb + c);
            }
            CPA_COMMIT();
        }

        // S = Q @ K^T for 32 keys (K [key][d] col-major kxn -> NON-trans ldsm)
        float4 s[2][4];
        #pragma unroll
        for (int mt = 0; mt < 2; mt++)
            #pragma unroll
            for (int nt = 0; nt < 4; nt++) s[mt][nt] = make_float4(0.f, 0.f, 0.f, 0.f);

        #pragma unroll
        for (int ntp = 0; ntp < 2; ntp++) {
            unsigned ka = kA + (kbase + ntp * 16) * 80;
            uint4 B0, B1;
            ldsm4(B0, ka);
            ldsm4(B1, ka + 32);
            #pragma unroll
            for (int mt = 0; mt < 2; mt++) {
                mma16(s[mt][2 * ntp],     aq[mt][0].x, aq[mt][0].y, aq[mt][0].z, aq[mt][0].w, B0.x, B0.z);
                mma16(s[mt][2 * ntp],     aq[mt][1].x, aq[mt][1].y, aq[mt][1].z, aq[mt][1].w, B1.x, B1.z);
                mma16(s[mt][2 * ntp + 1], aq[mt][0].x, aq[mt][0].y, aq[mt][0].z, aq[mt][0].w, B0.y, B0.w);
                mma16(s[mt][2 * ntp + 1], aq[mt][1].x, aq[mt][1].y, aq[mt][1].z, aq[mt][1].w, B1.y, B1.w);
            }
        }

        // V fragments hoisted: independent of S, LDSM latency hides under exp below
        uint4 Vf[2][2];
        #pragma unroll
        for (int ktp = 0; ktp < 2; ktp++) {
            unsigned va = vA + (kbase + ktp * 16) * 80;
            ldsm4t(Vf[ktp][0], va);
            ldsm4t(Vf[ktp][1], va + 32);
        }

        // bias (tb from smem) + pack-to-fp16 + packed ex2 (one MUFU per 2 elements)
        unsigned pa[2][2][4];
        #pragma unroll
        for (int mt = 0; mt < 2; mt++) {
            int qlo = q_row0 + mt * 16;
            #pragma unroll
            for (int nt = 0; nt < 4; nt++) {
                int lk = nt * 8 + 2 * tig;
                float2 tl = __half22float2(*(__half2*)&S.Tb[cur][qlo][lk]);
                float2 th = __half22float2(*(__half2*)&S.Tb[cur][qlo + 8][lk]);
                int c0 = kbase + lk;
                float mb0 = S.mbs[c0], mb1 = S.mbs[c0 + 1];
                unsigned alo = h2ex2(packh2(s[mt][nt].x + tl.x + mb0, s[mt][nt].y + tl.y + mb1));
                unsigned ahi = h2ex2(packh2(s[mt][nt].z + th.x + mb0, s[mt][nt].w + th.y + mb1));
                int ktp = nt >> 1;
                if (!(nt & 1)) {
                    pa[mt][ktp][0] = alo;
                    pa[mt][ktp][1] = ahi;
                } else {
                    pa[mt][ktp][2] = alo;
                    pa[mt][ktp][3] = ahi;
                }
            }
        }

        // O += P @ V, and l += P @ ones (extra column)
        #pragma unroll
        for (int ktp = 0; ktp < 2; ktp++) {
            #pragma unroll
            for (int mt = 0; mt < 2; mt++) {
                mma16(oacc[mt][0], pa[mt][ktp][0], pa[mt][ktp][1], pa[mt][ktp][2], pa[mt][ktp][3], Vf[ktp][0].x, Vf[ktp][0].y);
                mma16(oacc[mt][1], pa[mt][ktp][0], pa[mt][ktp][1], pa[mt][ktp][2], pa[mt][ktp][3], Vf[ktp][0].z, Vf[ktp][0].w);
                mma16(oacc[mt][2], pa[mt][ktp][0], pa[mt][ktp][1], pa[mt][ktp][2], pa[mt][ktp][3], Vf[ktp][1].x, Vf[ktp][1].y);
                mma16(oacc[mt][3], pa[mt][ktp][0], pa[mt][ktp][1], pa[mt][ktp][2], pa[mt][ktp][3], Vf[ktp][1].z, Vf[ktp][1].w);
                mma16(lacc[mt],    pa[mt][ktp][0], pa[mt][ktp][1], pa[mt][ktp][2], pa[mt][ktp][3], bone, bone);
            }
        }

        if (kb < 7) {
            CPA_WAIT0();
            __syncthreads();
        }
        cur ^= 1;
    }

    // finalize + gated store (l broadcast from tig==0 lanes)
    #pragma unroll
    for (int mt = 0; mt < 2; mt++) {
        float ll = __shfl_sync(FULL, lacc[mt].x, lane & ~3);
        float lh = __shfl_sync(FULL, lacc[mt].z, lane & ~3);
        float inv_lo = 1.f / ll, inv_hi = 1.f / lh;

        int q_lo = q_row0 + mt * 16, q_hi = q_lo + 8;
        size_t base_lo = ((size_t)(i * NN + q_lo)) * CIN + h * DD;
        size_t base_hi = ((size_t)(i * NN + q_hi)) * CIN + h * DD;
        #pragma unroll
        for (int ntd = 0; ntd < 4; ntd++) {
            int d0 = ntd * 8 + 2 * tig;
            float2 gl = __half22float2(*(__half2*)(g_gate + base_lo + d0));
            float2 gh = __half22float2(*(__half2*)(g_gate + base_hi + d0));
            *(__half2*)(g_o + base_lo + d0) =
                __floats2half2_rn(oacc[mt][ntd].x * inv_lo * gl.x, oacc[mt][ntd].y * inv_lo * gl.y);
            *(__half2*)(g_o + base_hi + d0) =
                __floats2half2_rn(oacc[mt][ntd].z * inv_hi * gh.x, oacc[mt][ntd].w * inv_hi * gh.y);
        }
    }
}

// ---------------- fp16-mma output projection: split-N (128 rows x 64 cols per CTA) ----------------
struct OutSmem {
    __half os[128][136];    // full 128-col activations
    __half Ws[128][72];     // this CTA's 64 weight cols
};

__global__ __launch_bounds__(256, 3) void outproj_kernel(float* __restrict__ out,
                                                         const float* __restrict__ bo) {
    extern __shared__ char sraw[];
    OutSmem& S = *(OutSmem*)sraw;

    int bid = blockIdx.x;
    int p0 = (bid >> 1) * 128;
    int n0 = (bid & 1) * 64;
    int t = threadIdx.x;
    int w = t >> 5, lane = t & 31;
    int gid = lane >> 2, tig = lane & 3;

    for (int f = t; f < 2048; f += 256) {
        int r = f >> 4, c8 = (f & 15) * 8;
        cpa16(cvta_s(&S.os[r][c8]), g_o + (size_t)(p0 + r) * CIN + c8);
    }
    for (int f = t; f < 1024; f += 256) {
        int r = f >> 3, c8 = (f & 7) * 8;
        cpa16(cvta_s(&S.Ws[r][c8]), &g_Woh[r][n0 + c8]);
    }
    CPA_COMMIT();
    CPA_WAIT0();
    __syncthreads();

    int wm = w >> 1, wn = w & 1;           // warp tile 32 rows x 32 cols
    int m8 = lane >> 3, r8 = lane & 7;

    unsigned aBase = cvta_s(&S.os[wm * 32 + (m8 & 1) * 8 + r8][(m8 >> 1) * 8]);
    unsigned bBase = cvta_s(&S.Ws[(m8 & 1) * 8 + r8][wn * 32 + (m8 >> 1) * 8]);

    float4 acc[2][4];
    #pragma unroll
    for (int mt = 0; mt < 2; mt++)
        #pragma unroll
        for (int nt = 0; nt < 4; nt++) acc[mt][nt] = make_float4(0.f, 0.f, 0.f, 0.f);

    #pragma unroll
    for (int ks = 0; ks < 8; ks++) {
        uint4 A0, A1, B0, B1;
        ldsm4(A0, aBase + ks * 32);
        ldsm4(A1, aBase + ks * 32 + 4352);   // +16 rows (16*272B)
        ldsm4t(B0, bBase + ks * 2304);       // +16 k-rows (16*144B)
        ldsm4t(B1, bBase + ks * 2304 + 32);  // +16 n-cols
        mma16(acc[0][0], A0.x, A0.y, A0.z, A0.w, B0.x, B0.y);
        mma16(acc[0][1], A0.x, A0.y, A0.z, A0.w, B0.z, B0.w);
        mma16(acc[0][2], A0.x, A0.y, A0.z, A0.w, B1.x, B1.y);
        mma16(acc[0][3], A0.x, A0.y, A0.z, A0.w, B1.z, B1.w);
        mma16(acc[1][0], A1.x, A1.y, A1.z, A1.w, B0.x, B0.y);
        mma16(acc[1][1], A1.x, A1.y, A1.z, A1.w, B0.z, B0.w);
        mma16(acc[1][2], A1.x, A1.y, A1.z, A1.w, B1.x, B1.y);
        mma16(acc[1][3], A1.x, A1.y, A1.z, A1.w, B1.z, B1.w);
    }

    #pragma unroll
    for (int mt = 0; mt < 2; mt++) {
        int p_lo = p0 + wm * 32 + mt * 16 + gid;
        int p_hi = p_lo + 8;
        #pragma unroll
        for (int nt = 0; nt < 4; nt++) {
            int c0 = n0 + wn * 32 + nt * 8 + 2 * tig;
            float2 bo2 = *(const float2*)(bo + c0);
            *(float2*)(out + (size_t)p_lo * CIN + c0) =
                make_float2(acc[mt][nt].x + bo2.x, acc[mt][nt].y + bo2.y);
            *(float2*)(out + (size_t)p_hi * CIN + c0) =
                make_float2(acc[mt][nt].z + bo2.x, acc[mt][nt].w + bo2.y);
        }
    }
}

extern "C" void kernel_launch(void* const* d_in, const int* in_sizes, int n_in,
                              void* d_out, int out_size) {
    (void)in_sizes; (void)n_in; (void)out_size;
    const float* x    = (const float*)d_in[0];
    const float* mask = (const float*)d_in[1];
    const float* lnw  = (const float*)d_in[2];
    const float* lnb  = (const float*)d_in[3];
    const float* wb   = (const float*)d_in[4];
    const float* wq   = (const float*)d_in[5];
    const float* wk   = (const float*)d_in[6];
    const float* wv   = (const float*)d_in[7];
    const float* wg   = (const float*)d_in[8];
    const float* bg   = (const float*)d_in[9];
    const float* wo   = (const float*)d_in[10];
    const float* bo   = (const float*)d_in[11];
    float* out = (float*)d_out;

    cudaFuncSetAttribute(lnproj_kernel,  cudaFuncAttributeMaxDynamicSharedMemorySize, (int)sizeof(LnSmem));
    cudaFuncSetAttribute(attn_kernel,    cudaFuncAttributeMaxDynamicSharedMemorySize, (int)sizeof(AttnSmem));
    cudaFuncSetAttribute(outproj_kernel, cudaFuncAttributeMaxDynamicSharedMemorySize, (int)sizeof(OutSmem));

    prep_kernel<<<256, 256>>>(wb, wq, wk, wv, wg, wo);
    lnproj_kernel<<<512, 256, sizeof(LnSmem)>>>(x, lnw, lnb, bg);
    attn_kernel<<<1024, 256, sizeof(AttnSmem)>>>(mask);
    outproj_kernel<<<1024, 256, sizeof(OutSmem)>>>(out, bo);
}